// round 7
// baseline (speedup 1.0000x reference)
#include <cuda_runtime.h>
#include <cstdint>

#define H        128
#define TE       128
#define THREADS  256
#define GRID_P   296          // 2 CTAs per SM

// Aggregation scratch (allocation-free rule: __device__ globals)
__device__ float g_sum[65536];
__device__ float g_cnt[65536];

// SMEM word (u32/float) offsets
#define OFF_FACT 0            // fp16 frag-major ACT: 8 mb x 8 kc x 32 x 4 = 8192
#define OFF_WF1  8192         // fp16 frag-major W1 (8 kc): 8192
#define OFF_WF2  16384        // fp16 frag-major W2 (8 kc): 8192
#define OFF_W0   24576        // fp32 plain W0 [4][128]: 512
#define OFF_B0   25088
#define OFF_B1   25216
#define OFF_B2   25344
#define OFF_W3   25472
#define OFF_RED  25600        // 512 floats: 4 n-groups x 128 rows
#define OFF_B3   26112
#define SMEM_WORDS 26116      // ~102 KB -> 2 CTAs/SM

__device__ __forceinline__ uint32_t pk16(float lo, float hi) {
    uint32_t u;
    asm("cvt.rn.f16x2.f32 %0, %1, %2;" : "=r"(u) : "f"(hi), "f"(lo));
    return u;
}

__device__ __forceinline__ void mma16(float* d, const uint32_t* a,
                                      uint32_t b0, uint32_t b1) {
    asm volatile("mma.sync.aligned.m16n8k16.row.col.f32.f16.f16.f32 "
        "{%0,%1,%2,%3}, {%4,%5,%6,%7}, {%8,%9}, {%0,%1,%2,%3};"
        : "+f"(d[0]), "+f"(d[1]), "+f"(d[2]), "+f"(d[3])
        : "r"(a[0]), "r"(a[1]), "r"(a[2]), "r"(a[3]), "r"(b0), "r"(b1));
}

// Stage W[K][H] (row-major, fp32) into fp16 B-fragment-major:
// WFu[((kc*8 + ncp)*32 + lane)*4 + r]
//   c=lane&3, g=lane>>2; n=(2*ncp + (r>>1))*8 + g
//   kbase = kc*16 + 2*c + (r&1)*8; word = pack(W[kbase][n], W[kbase+1][n])
__device__ void stage_w(const float* __restrict__ W,
                        uint32_t* __restrict__ WF, int tid) {
    for (int idx = tid; idx < 8 * 1024; idx += THREADS) {
        int r    = idx & 3;
        int lane = (idx >> 2) & 31;
        int ncp  = (idx >> 7) & 7;
        int kc   = idx >> 10;
        int c = lane & 3, g = lane >> 2;
        int n = (2 * ncp + (r >> 1)) * 8 + g;
        int kb = kc * 16 + 2 * c + ((r & 1) << 3);
        WF[idx] = pk16(W[kb * H + n], W[(kb + 1) * H + n]);
    }
}

// Mainloop: acc += ACT * W over 8 chunks of k=16.
__device__ __forceinline__ void layer_main(const uint32_t* __restrict__ smu,
                                           int wfOff, int m0, int n0, int lane,
                                           float acc[4][4][4]) {
    #pragma unroll
    for (int mc = 0; mc < 4; mc++)
        #pragma unroll
        for (int nc = 0; nc < 4; nc++)
            #pragma unroll
            for (int i = 0; i < 4; i++) acc[mc][nc][i] = 0.0f;

    const uint4* fact4 = (const uint4*)(smu + OFF_FACT);
    const uint4* wf    = (const uint4*)(smu + wfOff);
    const int mbb = m0 >> 4;

    #pragma unroll
    for (int kc = 0; kc < 8; kc++) {
        uint32_t a[4][4];
        #pragma unroll
        for (int mc = 0; mc < 4; mc++) {
            uint4 v = fact4[((mbb + mc) * 8 + kc) * 32 + lane];
            a[mc][0] = v.x; a[mc][1] = v.y; a[mc][2] = v.z; a[mc][3] = v.w;
        }
        uint32_t b[8];
        #pragma unroll
        for (int l = 0; l < 2; l++) {
            uint4 v = wf[(kc * 8 + (n0 >> 4) + l) * 32 + lane];
            b[l * 4 + 0] = v.x; b[l * 4 + 1] = v.y;
            b[l * 4 + 2] = v.z; b[l * 4 + 3] = v.w;
        }
        #pragma unroll
        for (int mc = 0; mc < 4; mc++)
            #pragma unroll
            for (int nc = 0; nc < 4; nc++) {
                int bi = (nc >> 1) * 4 + (nc & 1) * 2;
                mma16(acc[mc][nc], a[mc], b[bi], b[bi + 1]);
            }
    }
}

// Epilogue: relu(acc+bias) -> fp16 pack -> A-fragment slots (lane-local).
__device__ __forceinline__ void epi_write(uint32_t* __restrict__ smu,
                                          const float* __restrict__ bias,
                                          int m0, int n0, int lane,
                                          const float acc[4][4][4]) {
    const int q = lane & 3;
    uint4* fact4 = (uint4*)(smu + OFF_FACT);
    #pragma unroll
    for (int mc = 0; mc < 4; mc++) {
        int mb = (m0 >> 4) + mc;
        #pragma unroll
        for (int p = 0; p < 2; p++) {              // nc pair (2p, 2p+1)
            uint32_t w[4];
            #pragma unroll
            for (int h = 0; h < 2; h++) {          // nc = 2p+h
                int nc = 2 * p + h;
                int col = n0 + 8 * nc + 2 * q;
                float bb0 = bias[col], bb1 = bias[col + 1];
                w[2 * h + 0] = pk16(fmaxf(acc[mc][nc][0] + bb0, 0.0f),
                                    fmaxf(acc[mc][nc][1] + bb1, 0.0f));
                w[2 * h + 1] = pk16(fmaxf(acc[mc][nc][2] + bb0, 0.0f),
                                    fmaxf(acc[mc][nc][3] + bb1, 0.0f));
            }
            int kc = (n0 >> 4) + p;
            fact4[(mb * 8 + kc) * 32 + lane] = make_uint4(w[0], w[1], w[2], w[3]);
        }
    }
}

// ---------------------------------------------------------------------------
__global__ void node_kernel(const float* __restrict__ theta,
                            const float* __restrict__ v0p,
                            float* __restrict__ out, int N) {
    int i = blockIdx.x * blockDim.x + threadIdx.x;
    if (i < N) {
        float s, c;
        sincosf(theta[i], &s, &c);
        float v0 = *v0p;
        out[2 * i + 0] = v0 * c;
        out[2 * i + 1] = v0 * s;
        g_sum[i] = 0.0f;
        g_cnt[i] = 0.0f;
    }
}

// ---------------------------------------------------------------------------
__global__ __launch_bounds__(THREADS, 2)
void edge_kernel(const float* __restrict__ x, const float* __restrict__ theta,
                 const float* __restrict__ W0, const float* __restrict__ b0,
                 const float* __restrict__ W1, const float* __restrict__ b1,
                 const float* __restrict__ W2, const float* __restrict__ b2,
                 const float* __restrict__ W3, const float* __restrict__ b3,
                 const int* __restrict__ src, const int* __restrict__ dst,
                 int E, int nTiles) {
    extern __shared__ __align__(16) uint32_t smu[];
    float* smf = (float*)smu;
    const int tid  = threadIdx.x;
    const int wid  = tid >> 5;
    const int lane = tid & 31;

    // --- stage weights once per CTA ---
    stage_w(W1, smu + OFF_WF1, tid);
    stage_w(W2, smu + OFF_WF2, tid);
    for (int i = tid; i < 512; i += THREADS) smf[OFF_W0 + i] = W0[i];
    for (int i = tid; i < H; i += THREADS) {
        smf[OFF_B0 + i] = b0[i];
        smf[OFF_B1 + i] = b1[i];
        smf[OFF_B2 + i] = b2[i];
        smf[OFF_W3 + i] = W3[i];
    }
    if (tid == 0) smf[OFF_B3] = b3[0];
    __syncthreads();

    const int m0 = (wid & 1) * 64;
    const int n0 = (wid >> 1) * 32;
    const int ng = wid >> 1;
    float acc[4][4][4];

    // h0 phase constants: 2 threads per edge (j-halves), bank-rotated writes
    const int edge  = tid & 127;
    const int pbase = (tid >> 7) << 5;           // p range start: 0 or 32
    const int mb_e  = edge >> 4;
    const int r_e   = edge & 7;
    const int hi_e  = (edge >> 3) & 1;
    const int rot   = (tid >> 1) & 7;

    for (int tile = blockIdx.x; tile < nTiles; tile += gridDim.x) {
        const int ebase = tile * TE;

        // ---- features + SIMT layer0: h0 = relu(W0^T feat + b0) -> FACT ----
        {
            int e = ebase + edge;
            float f0 = 0.f, f1 = 0.f, f2 = 0.f, f3 = 0.f;
            if (e < E) {
                int is = src[e], id = dst[e];
                float xs = x[2 * is], ys = x[2 * is + 1];
                float xd = x[2 * id], yd = x[2 * id + 1];
                float ths = theta[is], thd = theta[id];
                float sn, cn; sincosf(thd - ths, &sn, &cn);
                float s0, c0; sincosf(ths, &s0, &c0);
                float drx = xd - xs, dry = yd - ys;
                f0 =  drx * c0 + dry * s0;
                f1 = -drx * s0 + dry * c0;
                f2 = cn; f3 = sn;
            }
            const float2* w0 = (const float2*)(smf + OFF_W0);
            const float2* bb = (const float2*)(smf + OFF_B0);
            #pragma unroll 8
            for (int pp = 0; pp < 32; pp++) {
                int p = pbase + (pp ^ rot);
                int jh = p;                        // j = 2p -> float2 index p
                float2 b  = bb[jh];
                float2 w0k = w0[jh];               // k=0 row
                float2 w1k = w0[64 + jh];          // k=1
                float2 w2k = w0[128 + jh];         // k=2
                float2 w3k = w0[192 + jh];         // k=3
                float ha = b.x + f0 * w0k.x + f1 * w1k.x + f2 * w2k.x + f3 * w3k.x;
                float hb = b.y + f0 * w0k.y + f1 * w1k.y + f2 * w2k.y + f3 * w3k.y;
                uint32_t w = pk16(fmaxf(ha, 0.f), fmaxf(hb, 0.f));
                // FACT word: ((mb*8+kc)*32 + r*4 + c)*4 + 2*khi + hi
                int word = ((mb_e * 8 + (p >> 3)) * 32 + r_e * 4 + (p & 3)) * 4
                         + 2 * ((p >> 2) & 1) + hi_e;
                smu[OFF_FACT + word] = w;
            }
        }
        __syncthreads();

        // ---- layer 1 ----
        layer_main(smu, OFF_WF1, m0, n0, lane, acc);
        __syncthreads();
        epi_write(smu, smf + OFF_B1, m0, n0, lane, acc);
        __syncthreads();

        // ---- layer 2 + fused final dot ----
        layer_main(smu, OFF_WF2, m0, n0, lane, acc);
        {
            const int r = lane >> 2, q = lane & 3;
            #pragma unroll
            for (int mc = 0; mc < 4; mc++) {
                float pa = 0.f, pb = 0.f;
                #pragma unroll
                for (int nc = 0; nc < 4; nc++) {
                    int col = n0 + 8 * nc + 2 * q;
                    float bb0 = smf[OFF_B2 + col], bb1 = smf[OFF_B2 + col + 1];
                    float w3a = smf[OFF_W3 + col], w3b = smf[OFF_W3 + col + 1];
                    pa += fmaxf(acc[mc][nc][0] + bb0, 0.f) * w3a;
                    pa += fmaxf(acc[mc][nc][1] + bb1, 0.f) * w3b;
                    pb += fmaxf(acc[mc][nc][2] + bb0, 0.f) * w3a;
                    pb += fmaxf(acc[mc][nc][3] + bb1, 0.f) * w3b;
                }
                pa += __shfl_xor_sync(0xffffffffu, pa, 1);
                pa += __shfl_xor_sync(0xffffffffu, pa, 2);
                pb += __shfl_xor_sync(0xffffffffu, pb, 1);
                pb += __shfl_xor_sync(0xffffffffu, pb, 2);
                if (q == 0) {
                    int row = m0 + 16 * mc + r;
                    smf[OFF_RED + ng * 128 + row]     = pa;
                    smf[OFF_RED + ng * 128 + row + 8] = pb;
                }
            }
        }
        __syncthreads();

        // ---- combine partials + scatter-add ----
        if (tid < TE) {
            int e = ebase + tid;
            if (e < E) {
                float msg = smf[OFF_RED + tid] + smf[OFF_RED + 128 + tid]
                          + smf[OFF_RED + 256 + tid] + smf[OFF_RED + 384 + tid]
                          + smf[OFF_B3];
                int d = dst[e];
                atomicAdd(&g_sum[d], msg);
                atomicAdd(&g_cnt[d], 1.0f);
            }
        }
        __syncthreads();
    }
}

// ---------------------------------------------------------------------------
__global__ void torque_kernel(float* __restrict__ out, int N) {
    int i = blockIdx.x * blockDim.x + threadIdx.x;
    if (i < N) out[2 * N + i] = g_sum[i] / fmaxf(g_cnt[i], 1.0f);
}

// ---------------------------------------------------------------------------
extern "C" void kernel_launch(void* const* d_in, const int* in_sizes, int n_in,
                              void* d_out, int out_size) {
    const float* x     = (const float*)d_in[0];
    const float* theta = (const float*)d_in[1];
    const float* v0    = (const float*)d_in[2];
    const float* W0    = (const float*)d_in[3];
    const float* b0    = (const float*)d_in[4];
    const float* W1    = (const float*)d_in[5];
    const float* b1    = (const float*)d_in[6];
    const float* W2    = (const float*)d_in[7];
    const float* b2    = (const float*)d_in[8];
    const float* W3    = (const float*)d_in[9];
    const float* b3    = (const float*)d_in[10];
    const int*   src   = (const int*)d_in[11];
    const int*   dst   = (const int*)d_in[12];

    int N = in_sizes[1];
    int E = in_sizes[11];
    int nTiles = (E + TE - 1) / TE;
    float* out = (float*)d_out;

    size_t smem = (size_t)SMEM_WORDS * sizeof(uint32_t);
    cudaFuncSetAttribute(edge_kernel,
                         cudaFuncAttributeMaxDynamicSharedMemorySize, (int)smem);

    int grid = GRID_P;
    if (nTiles < grid) grid = nTiles;

    node_kernel<<<(N + 255) / 256, 256>>>(theta, v0, out, N);
    edge_kernel<<<grid, THREADS, smem>>>(
        x, theta, W0, b0, W1, b1, W2, b2, W3, b3, src, dst, E, nTiles);
    torque_kernel<<<(N + 255) / 256, 256>>>(out, N);
}

// round 8
// speedup vs baseline: 1.3370x; 1.3370x over previous
#include <cuda_runtime.h>
#include <cstdint>

#define H        128
#define TE       128
#define THREADS  128
#define GRID_P   296          // 2 CTAs/SM, full residency (grid barrier safe)

// Aggregation scratch + barrier state (allocation-free rule: __device__ globals)
__device__ float g_sum[65536];
__device__ float g_cnt[65536];
__device__ unsigned g_barcnt = 0;
__device__ volatile unsigned g_sense = 0;

// SMEM word (u32/float) offsets
#define OFF_FACT 0            // fp16 frag-major ACT: 8 mb x 8 kc x 32 x 4 = 8192
#define OFF_WF0  8192         // fp16 frag-major W0 (1 kc):  1024
#define OFF_WF1  9216         // fp16 frag-major W1 (8 kc):  8192
#define OFF_WF2  17408        // fp16 frag-major W2 (8 kc):  8192
#define OFF_B0   25600
#define OFF_B1   25728
#define OFF_B2   25856
#define OFF_W3   25984
#define OFF_RED  26112        // 256 floats: 2 n-groups x 128 rows
#define OFF_B3   26368
#define SMEM_WORDS 26372      // ~103 KB -> 2 CTAs/SM

__device__ __forceinline__ uint32_t pk16(float lo, float hi) {
    uint32_t u;
    asm("cvt.rn.f16x2.f32 %0, %1, %2;" : "=r"(u) : "f"(hi), "f"(lo));
    return u;
}

__device__ __forceinline__ void mma16(float* d, const uint32_t* a,
                                      uint32_t b0, uint32_t b1) {
    asm volatile("mma.sync.aligned.m16n8k16.row.col.f32.f16.f16.f32 "
        "{%0,%1,%2,%3}, {%4,%5,%6,%7}, {%8,%9}, {%0,%1,%2,%3};"
        : "+f"(d[0]), "+f"(d[1]), "+f"(d[2]), "+f"(d[3])
        : "r"(a[0]), "r"(a[1]), "r"(a[2]), "r"(a[3]), "r"(b0), "r"(b1));
}

// Sense-reversing grid barrier. Safe: grid == resident CTA count.
__device__ __forceinline__ void grid_bar() {
    __syncthreads();
    if (threadIdx.x == 0) {
        unsigned s = g_sense;
        __threadfence();
        if (atomicAdd(&g_barcnt, 1u) == gridDim.x - 1) {
            g_barcnt = 0;
            __threadfence();
            g_sense = s ^ 1u;
        } else {
            while (g_sense == s) { }
        }
        __threadfence();
    }
    __syncthreads();
}

// Stage W[K][H] (row-major, fp32) into fp16 B-fragment-major (proven R6 map):
// WFu[((kc*8 + ncp)*32 + lane)*4 + r]
__device__ void stage_w(const float* __restrict__ W, int KC16, int Kreal,
                        uint32_t* __restrict__ WF, int tid) {
    int total = KC16 * 1024;
    for (int idx = tid; idx < total; idx += THREADS) {
        int r    = idx & 3;
        int lane = (idx >> 2) & 31;
        int ncp  = (idx >> 7) & 7;
        int kc   = idx >> 10;
        int c = lane & 3, g = lane >> 2;
        int n = (2 * ncp + (r >> 1)) * 8 + g;
        int kb = kc * 16 + 2 * c + ((r & 1) << 3);
        float lo = (kb     < Kreal) ? W[kb * H + n]       : 0.0f;
        float hi = (kb + 1 < Kreal) ? W[(kb + 1) * H + n] : 0.0f;
        WF[idx] = pk16(lo, hi);
    }
}

// Mainloop: warp tile m=64 x n=64. acc[mc 0..3][nc 0..7][4].
template<int KC16>
__device__ __forceinline__ void layer_main(const uint32_t* __restrict__ smu,
                                           int wfOff, int m0, int n0, int lane,
                                           float acc[4][8][4]) {
    #pragma unroll
    for (int mc = 0; mc < 4; mc++)
        #pragma unroll
        for (int nc = 0; nc < 8; nc++)
            #pragma unroll
            for (int i = 0; i < 4; i++) acc[mc][nc][i] = 0.0f;

    const uint4* fact4 = (const uint4*)(smu + OFF_FACT);
    const uint4* wf    = (const uint4*)(smu + wfOff);
    const int mbb = m0 >> 4;
    const int nb  = n0 >> 4;

    #pragma unroll
    for (int kc = 0; kc < KC16; kc++) {
        uint32_t a[4][4];
        #pragma unroll
        for (int mc = 0; mc < 4; mc++) {
            uint4 v = fact4[((mbb + mc) * 8 + kc) * 32 + lane];
            a[mc][0] = v.x; a[mc][1] = v.y; a[mc][2] = v.z; a[mc][3] = v.w;
        }
        uint32_t b[4][4];
        #pragma unroll
        for (int l = 0; l < 4; l++) {
            uint4 v = wf[(kc * 8 + nb + l) * 32 + lane];
            b[l][0] = v.x; b[l][1] = v.y; b[l][2] = v.z; b[l][3] = v.w;
        }
        #pragma unroll
        for (int mc = 0; mc < 4; mc++)
            #pragma unroll
            for (int nc = 0; nc < 8; nc++) {
                int pr = nc >> 1, h = nc & 1;
                mma16(acc[mc][nc], a[mc], b[pr][2 * h], b[pr][2 * h + 1]);
            }
    }
}

// Epilogue: relu(acc+bias) -> fp16 -> A-fragment slots (lane-local, proven map).
__device__ __forceinline__ void epi_write(uint32_t* __restrict__ smu,
                                          const float* __restrict__ bias,
                                          int m0, int n0, int lane,
                                          const float acc[4][8][4]) {
    const int q = lane & 3;
    uint4* fact4 = (uint4*)(smu + OFF_FACT);
    #pragma unroll
    for (int mc = 0; mc < 4; mc++) {
        int mb = (m0 >> 4) + mc;
        #pragma unroll
        for (int p = 0; p < 4; p++) {              // nc pair (2p, 2p+1)
            uint32_t w[4];
            #pragma unroll
            for (int h = 0; h < 2; h++) {
                int nc = 2 * p + h;
                int col = n0 + 8 * nc + 2 * q;
                float bb0 = bias[col], bb1 = bias[col + 1];
                w[2 * h + 0] = pk16(fmaxf(acc[mc][nc][0] + bb0, 0.0f),
                                    fmaxf(acc[mc][nc][1] + bb1, 0.0f));
                w[2 * h + 1] = pk16(fmaxf(acc[mc][nc][2] + bb0, 0.0f),
                                    fmaxf(acc[mc][nc][3] + bb1, 0.0f));
            }
            int kc = (n0 >> 4) + p;
            fact4[(mb * 8 + kc) * 32 + lane] = make_uint4(w[0], w[1], w[2], w[3]);
        }
    }
}

// ---------------------------------------------------------------------------
// Single persistent kernel: velocity+zero | grid_bar | edge tiles | grid_bar | torque
// ---------------------------------------------------------------------------
__global__ __launch_bounds__(THREADS, 2)
void fused_kernel(const float* __restrict__ x, const float* __restrict__ theta,
                  const float* __restrict__ v0p,
                  const float* __restrict__ W0, const float* __restrict__ b0,
                  const float* __restrict__ W1, const float* __restrict__ b1,
                  const float* __restrict__ W2, const float* __restrict__ b2,
                  const float* __restrict__ W3, const float* __restrict__ b3,
                  const int* __restrict__ src, const int* __restrict__ dst,
                  float* __restrict__ out, int N, int E, int nTiles) {
    extern __shared__ __align__(16) uint32_t smu[];
    float* smf = (float*)smu;
    const int tid  = threadIdx.x;
    const int wid  = tid >> 5;
    const int lane = tid & 31;

    // ---- phase A: velocity + zero aggregation scratch ----
    {
        float v0 = *v0p;
        for (int i = blockIdx.x * THREADS + tid; i < N; i += gridDim.x * THREADS) {
            float s, c;
            sincosf(theta[i], &s, &c);
            out[2 * i + 0] = v0 * c;
            out[2 * i + 1] = v0 * s;
            g_sum[i] = 0.0f;
            g_cnt[i] = 0.0f;
        }
    }

    // ---- stage weights once per CTA (overlaps with other CTAs' phase A) ----
    stage_w(W0, 1, 4,   smu + OFF_WF0, tid);
    stage_w(W1, 8, 128, smu + OFF_WF1, tid);
    stage_w(W2, 8, 128, smu + OFF_WF2, tid);
    if (tid < H) {
        smf[OFF_B0 + tid] = b0[tid];
        smf[OFF_B1 + tid] = b1[tid];
        smf[OFF_B2 + tid] = b2[tid];
        smf[OFF_W3 + tid] = W3[tid];
    }
    if (tid == 0) smf[OFF_B3] = b3[0];

    grid_bar();   // zeroing complete everywhere before any atomics

    const int m0 = (wid & 1) * 64;
    const int n0 = (wid >> 1) * 64;
    const int ng = wid >> 1;
    float acc[4][8][4];

    for (int tile = blockIdx.x; tile < nTiles; tile += gridDim.x) {
        const int ebase = tile * TE;

        // ---- features -> FACT kc=0 (fragment layout, proven R6 map) ----
        {
            int e = ebase + tid;
            float v0f = 0.f, v1f = 0.f, v2f = 0.f, v3f = 0.f;
            if (e < E) {
                int is = src[e], id = dst[e];
                float xs = x[2 * is], ys = x[2 * is + 1];
                float xd = x[2 * id], yd = x[2 * id + 1];
                float ths = theta[is], thd = theta[id];
                float sn, cn; sincosf(thd - ths, &sn, &cn);
                float s0, c0; sincosf(ths, &s0, &c0);
                float drx = xd - xs, dry = yd - ys;
                v0f =  drx * c0 + dry * s0;
                v1f = -drx * s0 + dry * c0;
                v2f = cn; v3f = sn;
            }
            int mb = tid >> 4, row16 = tid & 15, r = row16 & 7, hi = row16 >> 3;
            uint32_t base = ((mb * 8) * 32 + r * 4) * 4;
            #pragma unroll
            for (int c = 0; c < 4; c++) {
                uint32_t w = (c == 0) ? pk16(v0f, v1f)
                           : (c == 1) ? pk16(v2f, v3f) : 0u;
                smu[OFF_FACT + base + c * 4 + hi]     = w;   // k<8
                smu[OFF_FACT + base + c * 4 + 2 + hi] = 0u;  // k>=8
            }
        }
        __syncthreads();

        // ---- layer 0 (MMA, KC=1) ----
        layer_main<1>(smu, OFF_WF0, m0, n0, lane, acc);
        __syncthreads();
        epi_write(smu, smf + OFF_B0, m0, n0, lane, acc);
        __syncthreads();

        // ---- layer 1 ----
        layer_main<8>(smu, OFF_WF1, m0, n0, lane, acc);
        __syncthreads();
        epi_write(smu, smf + OFF_B1, m0, n0, lane, acc);
        __syncthreads();

        // ---- layer 2 + fused final dot (h2 never touches smem) ----
        layer_main<8>(smu, OFF_WF2, m0, n0, lane, acc);
        {
            const int r = lane >> 2, q = lane & 3;
            #pragma unroll
            for (int mc = 0; mc < 4; mc++) {
                float pa = 0.f, pb = 0.f;
                #pragma unroll
                for (int nc = 0; nc < 8; nc++) {
                    int col = n0 + 8 * nc + 2 * q;
                    float bb0 = smf[OFF_B2 + col], bb1 = smf[OFF_B2 + col + 1];
                    float w3a = smf[OFF_W3 + col], w3b = smf[OFF_W3 + col + 1];
                    pa += fmaxf(acc[mc][nc][0] + bb0, 0.f) * w3a;
                    pa += fmaxf(acc[mc][nc][1] + bb1, 0.f) * w3b;
                    pb += fmaxf(acc[mc][nc][2] + bb0, 0.f) * w3a;
                    pb += fmaxf(acc[mc][nc][3] + bb1, 0.f) * w3b;
                }
                pa += __shfl_xor_sync(0xffffffffu, pa, 1);
                pa += __shfl_xor_sync(0xffffffffu, pa, 2);
                pb += __shfl_xor_sync(0xffffffffu, pb, 1);
                pb += __shfl_xor_sync(0xffffffffu, pb, 2);
                if (q == 0) {
                    int row = m0 + 16 * mc + r;
                    smf[OFF_RED + ng * 128 + row]     = pa;
                    smf[OFF_RED + ng * 128 + row + 8] = pb;
                }
            }
        }
        __syncthreads();

        // ---- combine n-group partials + scatter-add ----
        {
            int e = ebase + tid;
            if (e < E) {
                float msg = smf[OFF_RED + tid] + smf[OFF_RED + 128 + tid]
                          + smf[OFF_B3];
                int d = dst[e];
                atomicAdd(&g_sum[d], msg);
                atomicAdd(&g_cnt[d], 1.0f);
            }
        }
        __syncthreads();
    }

    __threadfence();   // publish this CTA's atomics before the barrier
    grid_bar();

    // ---- phase C: torque = mean ----
    for (int i = blockIdx.x * THREADS + tid; i < N; i += gridDim.x * THREADS)
        out[2 * N + i] = g_sum[i] / fmaxf(g_cnt[i], 1.0f);
}

// ---------------------------------------------------------------------------
extern "C" void kernel_launch(void* const* d_in, const int* in_sizes, int n_in,
                              void* d_out, int out_size) {
    const float* x     = (const float*)d_in[0];
    const float* theta = (const float*)d_in[1];
    const float* v0    = (const float*)d_in[2];
    const float* W0    = (const float*)d_in[3];
    const float* b0    = (const float*)d_in[4];
    const float* W1    = (const float*)d_in[5];
    const float* b1    = (const float*)d_in[6];
    const float* W2    = (const float*)d_in[7];
    const float* b2    = (const float*)d_in[8];
    const float* W3    = (const float*)d_in[9];
    const float* b3    = (const float*)d_in[10];
    const int*   src   = (const int*)d_in[11];
    const int*   dst   = (const int*)d_in[12];

    int N = in_sizes[1];
    int E = in_sizes[11];
    int nTiles = (E + TE - 1) / TE;
    float* out = (float*)d_out;

    size_t smem = (size_t)SMEM_WORDS * sizeof(uint32_t);
    cudaFuncSetAttribute(fused_kernel,
                         cudaFuncAttributeMaxDynamicSharedMemorySize, (int)smem);

    fused_kernel<<<GRID_P, THREADS, smem>>>(
        x, theta, v0, W0, b0, W1, b1, W2, b2, W3, b3, src, dst,
        out, N, E, nTiles);
}